// round 1
// baseline (speedup 1.0000x reference)
#include <cuda_runtime.h>

#define NB 2
#define P  8192
#define HH 48
#define WW 48
#define RH 95
#define RW 95
#define QQ (RH*RW)          // 9025
#define TILE 2048           // float4 tile in smem = 32KB
#define BLK_A 128
#define GRID_A (P/BLK_A)    // 64
#define BLK_B 128
#define GRID_B ((QQ + BLK_B - 1)/BLK_B)  // 71

// scratch (allocation-free rule: __device__ globals)
__device__ float4 g_mesh[NB*QQ];
__device__ float4 g_pc[NB*P];
__device__ float  g_partA[NB*GRID_A];   // 128
__device__ float  g_partB[NB*GRID_B];   // 142

// ---------------------------------------------------------------------------
// prep: refine mesh (midpoint bilinear, align_corners) + pack clouds as
// float4(x, y, z, 0.5*|v|^2)
// ---------------------------------------------------------------------------
__global__ void prep_kernel(const float* __restrict__ verts,
                            const float* __restrict__ pc)
{
    int idx = blockIdx.x * blockDim.x + threadIdx.x;
    if (idx < NB*QQ) {
        int n = idx / QQ;
        int r = idx % QQ;
        int i = r / RW, j = r % RW;
        int i0 = i >> 1, j0 = j >> 1;
        int oi = i & 1,  oj = j & 1;
        const float* base = verts + n * 3 * HH * WW;
        float vv[3];
        #pragma unroll
        for (int c = 0; c < 3; c++) {
            const float* pl = base + c * HH * WW;
            float v00 = pl[i0*WW + j0];
            float top = v00;
            if (oj) top = 0.5f * (v00 + pl[i0*WW + j0 + 1]);
            float val = top;
            if (oi) {
                float v10 = pl[(i0+1)*WW + j0];
                float bot = v10;
                if (oj) bot = 0.5f * (v10 + pl[(i0+1)*WW + j0 + 1]);
                val = 0.5f * (top + bot);
            }
            vv[c] = val;
        }
        g_mesh[idx] = make_float4(vv[0], vv[1], vv[2],
                                  0.5f*(vv[0]*vv[0] + vv[1]*vv[1] + vv[2]*vv[2]));
    } else {
        int idx2 = idx - NB*QQ;
        if (idx2 < NB*P) {
            const float* s = pc + (size_t)idx2 * 3;
            float x = s[0], y = s[1], z = s[2];
            g_pc[idx2] = make_float4(x, y, z, 0.5f*(x*x + y*y + z*z));
        }
    }
}

// ---------------------------------------------------------------------------
// block sum reduction (blockDim multiple of 32, <=1024)
// ---------------------------------------------------------------------------
__device__ __forceinline__ float block_reduce_sum(float v)
{
    __shared__ float sh[32];
    #pragma unroll
    for (int o = 16; o > 0; o >>= 1) v += __shfl_down_sync(0xffffffffu, v, o);
    int lane = threadIdx.x & 31, wid = threadIdx.x >> 5;
    if (lane == 0) sh[wid] = v;
    __syncthreads();
    int nw = blockDim.x >> 5;
    v = (threadIdx.x < nw) ? sh[lane] : 0.0f;
    if (wid == 0) {
        #pragma unroll
        for (int o = 16; o > 0; o >>= 1) v += __shfl_down_sync(0xffffffffu, v, o);
    }
    return v;  // valid in thread 0
}

// ---------------------------------------------------------------------------
// Per pair: s = a.b - 0.5|b|^2 ; min_d = 2*(0.5|a|^2 - max_q s)
// identical algebra to the reference's a2+b2-2ab.
// ---------------------------------------------------------------------------
__device__ __forceinline__ void chamfer_dir(const float4* __restrict__ A,
                                            int nA, const float4* __restrict__ B,
                                            int nB_pts, float* __restrict__ part)
{
    __shared__ float4 sm[TILE];
    int n = blockIdx.y;
    int praw = blockIdx.x * blockDim.x + threadIdx.x;
    int p = praw < nA ? praw : nA - 1;       // clamp; masked out at the end
    float4 a = A[n * nA + p];

    float b0m = -3.4e38f, b1m = -3.4e38f, b2m = -3.4e38f, b3m = -3.4e38f;

    const float4* Bn = B + n * nB_pts;
    for (int q0 = 0; q0 < nB_pts; q0 += TILE) {
        int cnt = min(TILE, nB_pts - q0);
        __syncthreads();
        for (int t = threadIdx.x; t < cnt; t += blockDim.x)
            sm[t] = Bn[q0 + t];
        __syncthreads();

        int t = 0;
        for (; t + 4 <= cnt; t += 4) {
            float4 b0 = sm[t], b1 = sm[t+1], b2 = sm[t+2], b3 = sm[t+3];
            float s0 = fmaf(a.x, b0.x, fmaf(a.y, b0.y, fmaf(a.z, b0.z, -b0.w)));
            float s1 = fmaf(a.x, b1.x, fmaf(a.y, b1.y, fmaf(a.z, b1.z, -b1.w)));
            float s2 = fmaf(a.x, b2.x, fmaf(a.y, b2.y, fmaf(a.z, b2.z, -b2.w)));
            float s3 = fmaf(a.x, b3.x, fmaf(a.y, b3.y, fmaf(a.z, b3.z, -b3.w)));
            b0m = fmaxf(b0m, s0);
            b1m = fmaxf(b1m, s1);
            b2m = fmaxf(b2m, s2);
            b3m = fmaxf(b3m, s3);
        }
        for (; t < cnt; t++) {
            float4 b = sm[t];
            float s = fmaf(a.x, b.x, fmaf(a.y, b.y, fmaf(a.z, b.z, -b.w)));
            b0m = fmaxf(b0m, s);
        }
    }

    float best = fmaxf(fmaxf(b0m, b1m), fmaxf(b2m, b3m));
    float mind = 2.0f * (a.w - best);
    if (praw >= nA) mind = 0.0f;

    float bsum = block_reduce_sum(mind);
    if (threadIdx.x == 0)
        part[blockIdx.y * gridDim.x + blockIdx.x] = bsum;
}

__global__ void chamferA_kernel() { chamfer_dir(g_pc,   P,  g_mesh, QQ, g_partA); }
__global__ void chamferB_kernel() { chamfer_dir(g_mesh, QQ, g_pc,   P,  g_partB); }

// ---------------------------------------------------------------------------
// finalize: deterministic reduction of partial sums
// ---------------------------------------------------------------------------
__global__ void finalize_kernel(float* __restrict__ out)
{
    float v = 0.0f;
    int tid = threadIdx.x;
    for (int i = tid; i < NB*GRID_A; i += blockDim.x) v += g_partA[i] * (1.0f/(NB*P));
    for (int i = tid; i < NB*GRID_B; i += blockDim.x) v += g_partB[i] * (1.0f/(NB*QQ));
    // warp reduce (blockDim = 32)
    #pragma unroll
    for (int o = 16; o > 0; o >>= 1) v += __shfl_down_sync(0xffffffffu, v, o);
    if (tid == 0) out[0] = v;
}

extern "C" void kernel_launch(void* const* d_in, const int* in_sizes, int n_in,
                              void* d_out, int out_size)
{
    // resolve inputs by size: vertices = 2*3*48*48 = 13824, pc = 2*8192*3 = 49152
    const float* verts = (const float*)d_in[0];
    const float* pc    = (const float*)d_in[1];
    if (n_in >= 2 && in_sizes[0] != NB*3*HH*WW) {
        verts = (const float*)d_in[1];
        pc    = (const float*)d_in[0];
    }

    int prep_items = NB*QQ + NB*P;  // 34434
    prep_kernel<<<(prep_items + 255)/256, 256>>>(verts, pc);

    chamferA_kernel<<<dim3(GRID_A, NB), BLK_A>>>();
    chamferB_kernel<<<dim3(GRID_B, NB), BLK_B>>>();

    finalize_kernel<<<1, 32>>>((float*)d_out);
}

// round 3
// speedup vs baseline: 1.4578x; 1.4578x over previous
#include <cuda_runtime.h>

#define NB 2
#define P  8192
#define HH 48
#define WW 48
#define RH 95
#define RW 95
#define QQ (RH*RW)          // 9025
#define TILE 2048           // SoA tile: 4 arrays x 2048 floats = 32KB
#define BLK 128
#define RPT 2               // a-points per thread

// grid decomposition (combined chamfer kernel)
#define XB_A 32             // 8192 / (128*2) per batch
#define XB_B 36             // ceil(9025 / (128*2)) per batch
#define CTAS_A (NB*XB_A)    // 64
#define CTAS_B (NB*XB_B)    // 72
#define CTAS_TOT (CTAS_A + CTAS_B)  // 136

// scratch (allocation-free rule: __device__ globals)
__device__ float4 g_mesh[NB*QQ];
__device__ float4 g_pc[NB*P];
__device__ float  g_partA[CTAS_A];
__device__ float  g_partB[CTAS_B];

// ---------------------------------------------------------------------------
// f32x2 packed helpers
// ---------------------------------------------------------------------------
__device__ __forceinline__ unsigned long long fma2(unsigned long long a,
                                                   unsigned long long b,
                                                   unsigned long long c)
{
    unsigned long long d;
    asm("fma.rn.f32x2 %0, %1, %2, %3;" : "=l"(d) : "l"(a), "l"(b), "l"(c));
    return d;
}
__device__ __forceinline__ unsigned long long pack2(float x, float y)
{
    unsigned long long r;
    asm("mov.b64 %0, {%1,%2};" : "=l"(r) : "f"(x), "f"(y));
    return r;
}
__device__ __forceinline__ float2 u2f(unsigned long long v)
{
    float2 r;
    asm("mov.b64 {%0,%1}, %2;" : "=f"(r.x), "=f"(r.y) : "l"(v));
    return r;
}

// ---------------------------------------------------------------------------
// prep: refine mesh (midpoint bilinear, align_corners) + pack clouds as
// float4(x, y, z, 0.5*|v|^2)
// ---------------------------------------------------------------------------
__global__ void prep_kernel(const float* __restrict__ verts,
                            const float* __restrict__ pc)
{
    int idx = blockIdx.x * blockDim.x + threadIdx.x;
    if (idx < NB*QQ) {
        int n = idx / QQ;
        int r = idx % QQ;
        int i = r / RW, j = r % RW;
        int i0 = i >> 1, j0 = j >> 1;
        int oi = i & 1,  oj = j & 1;
        const float* base = verts + n * 3 * HH * WW;
        float vv[3];
        #pragma unroll
        for (int c = 0; c < 3; c++) {
            const float* pl = base + c * HH * WW;
            float v00 = pl[i0*WW + j0];
            float top = v00;
            if (oj) top = 0.5f * (v00 + pl[i0*WW + j0 + 1]);
            float val = top;
            if (oi) {
                float v10 = pl[(i0+1)*WW + j0];
                float bot = v10;
                if (oj) bot = 0.5f * (v10 + pl[(i0+1)*WW + j0 + 1]);
                val = 0.5f * (top + bot);
            }
            vv[c] = val;
        }
        g_mesh[idx] = make_float4(vv[0], vv[1], vv[2],
                                  0.5f*(vv[0]*vv[0] + vv[1]*vv[1] + vv[2]*vv[2]));
    } else {
        int idx2 = idx - NB*QQ;
        if (idx2 < NB*P) {
            const float* s = pc + (size_t)idx2 * 3;
            float x = s[0], y = s[1], z = s[2];
            g_pc[idx2] = make_float4(x, y, z, 0.5f*(x*x + y*y + z*z));
        }
    }
}

// ---------------------------------------------------------------------------
// block sum reduction (blockDim = 128)
// ---------------------------------------------------------------------------
__device__ __forceinline__ float block_reduce_sum(float v)
{
    __shared__ float sh[4];
    #pragma unroll
    for (int o = 16; o > 0; o >>= 1) v += __shfl_down_sync(0xffffffffu, v, o);
    int lane = threadIdx.x & 31, wid = threadIdx.x >> 5;
    if (lane == 0) sh[wid] = v;
    __syncthreads();
    if (wid == 0) {
        v = (lane < 4) ? sh[lane] : 0.0f;
        #pragma unroll
        for (int o = 2; o > 0; o >>= 1) v += __shfl_down_sync(0xffffffffu, v, o);
    }
    return v;  // valid in thread 0
}

// ---------------------------------------------------------------------------
// One chamfer direction, SoA broadcast + f32x2.
//   s = a.b - 0.5|b|^2 ; min_d = 2*(0.5|a|^2 - max_b s)
// Each thread owns RPT=2 consecutive a-points; inner loop walks the shared
// SoA b-tile 4 points at a time (unrolled x2 -> 8/iter), every lane reading
// the same addresses (broadcast) as packed f32x2 operands.
// ---------------------------------------------------------------------------
__device__ __forceinline__ void chamfer_quad(
    unsigned long long ax0, unsigned long long ay0, unsigned long long az0,
    unsigned long long ax1, unsigned long long ay1, unsigned long long az1,
    const float* sbx, const float* sby, const float* sbz, const float* sbw,
    int t, float& m0a, float& m0b, float& m1a, float& m1b)
{
    ulonglong2 X = *(const ulonglong2*)(sbx + t);
    ulonglong2 Y = *(const ulonglong2*)(sby + t);
    ulonglong2 Z = *(const ulonglong2*)(sbz + t);
    ulonglong2 W = *(const ulonglong2*)(sbw + t);

    unsigned long long s;
    float2 f;
    s = fma2(az0, Z.x, W.x); s = fma2(ay0, Y.x, s); s = fma2(ax0, X.x, s);
    f = u2f(s); m0a = fmaxf(m0a, f.x); m0b = fmaxf(m0b, f.y);
    s = fma2(az0, Z.y, W.y); s = fma2(ay0, Y.y, s); s = fma2(ax0, X.y, s);
    f = u2f(s); m0a = fmaxf(m0a, f.x); m0b = fmaxf(m0b, f.y);
    s = fma2(az1, Z.x, W.x); s = fma2(ay1, Y.x, s); s = fma2(ax1, X.x, s);
    f = u2f(s); m1a = fmaxf(m1a, f.x); m1b = fmaxf(m1b, f.y);
    s = fma2(az1, Z.y, W.y); s = fma2(ay1, Y.y, s); s = fma2(ax1, X.y, s);
    f = u2f(s); m1a = fmaxf(m1a, f.x); m1b = fmaxf(m1b, f.y);
}

__device__ __forceinline__ void chamfer_dir(const float4* __restrict__ A,
                                            int nA,
                                            const float4* __restrict__ B,
                                            int nB_pts,
                                            float* __restrict__ part_slot,
                                            int xb, int n)
{
    __shared__ __align__(16) float sbx[TILE];
    __shared__ __align__(16) float sby[TILE];
    __shared__ __align__(16) float sbz[TILE];
    __shared__ __align__(16) float sbw[TILE];

    int tid = threadIdx.x;
    int a_base = (xb * BLK + tid) * RPT;
    int i0 = a_base     < nA ? a_base     : nA - 1;
    int i1 = a_base + 1 < nA ? a_base + 1 : nA - 1;
    float4 a0 = A[n * nA + i0];
    float4 a1 = A[n * nA + i1];

    unsigned long long ax0 = pack2(a0.x, a0.x), ay0 = pack2(a0.y, a0.y), az0 = pack2(a0.z, a0.z);
    unsigned long long ax1 = pack2(a1.x, a1.x), ay1 = pack2(a1.y, a1.y), az1 = pack2(a1.z, a1.z);

    float m0a = -3.0e38f, m0b = -3.0e38f;
    float m1a = -3.0e38f, m1b = -3.0e38f;

    const float4* Bn = B + n * nB_pts;
    for (int q0 = 0; q0 < nB_pts; q0 += TILE) {
        int cnt  = min(TILE, nB_pts - q0);
        int cntp = (cnt + 7) & ~7;           // pad to multiple of 8
        __syncthreads();
        for (int t = tid; t < cntp; t += BLK) {
            if (t < cnt) {
                float4 b = Bn[q0 + t];
                sbx[t] = b.x; sby[t] = b.y; sbz[t] = b.z; sbw[t] = -b.w;
            } else {
                sbx[t] = 0.0f; sby[t] = 0.0f; sbz[t] = 0.0f; sbw[t] = -3.0e38f;
            }
        }
        __syncthreads();

        #pragma unroll 1
        for (int t = 0; t < cntp; t += 8) {
            chamfer_quad(ax0, ay0, az0, ax1, ay1, az1,
                         sbx, sby, sbz, sbw, t,     m0a, m0b, m1a, m1b);
            chamfer_quad(ax0, ay0, az0, ax1, ay1, az1,
                         sbx, sby, sbz, sbw, t + 4, m0a, m0b, m1a, m1b);
        }
    }

    float mind0 = 2.0f * (a0.w - fmaxf(m0a, m0b));
    float mind1 = 2.0f * (a1.w - fmaxf(m1a, m1b));
    if (a_base     >= nA) mind0 = 0.0f;
    if (a_base + 1 >= nA) mind1 = 0.0f;

    float bsum = block_reduce_sum(mind0 + mind1);
    if (tid == 0) *part_slot = bsum;
}

// ---------------------------------------------------------------------------
// Combined chamfer: both directions, both batches, one grid (136 CTAs)
// ---------------------------------------------------------------------------
__global__ void __launch_bounds__(BLK, 1) chamfer_kernel()
{
    int bid = blockIdx.x;
    if (bid < CTAS_A) {
        int n = bid / XB_A, xb = bid % XB_A;
        chamfer_dir(g_pc, P, g_mesh, QQ, &g_partA[bid], xb, n);
    } else {
        int b2 = bid - CTAS_A;
        int n = b2 / XB_B, xb = b2 % XB_B;
        chamfer_dir(g_mesh, QQ, g_pc, P, &g_partB[b2], xb, n);
    }
}

// ---------------------------------------------------------------------------
// finalize: deterministic reduction of partial sums
// ---------------------------------------------------------------------------
__global__ void finalize_kernel(float* __restrict__ out)
{
    float v = 0.0f;
    int tid = threadIdx.x;
    for (int i = tid; i < CTAS_A; i += 32) v += g_partA[i] * (1.0f/(NB*P));
    for (int i = tid; i < CTAS_B; i += 32) v += g_partB[i] * (1.0f/(NB*QQ));
    #pragma unroll
    for (int o = 16; o > 0; o >>= 1) v += __shfl_down_sync(0xffffffffu, v, o);
    if (tid == 0) out[0] = v;
}

extern "C" void kernel_launch(void* const* d_in, const int* in_sizes, int n_in,
                              void* d_out, int out_size)
{
    // resolve inputs by size: vertices = 2*3*48*48 = 13824, pc = 2*8192*3 = 49152
    const float* verts = (const float*)d_in[0];
    const float* pc    = (const float*)d_in[1];
    if (n_in >= 2 && in_sizes[0] != NB*3*HH*WW) {
        verts = (const float*)d_in[1];
        pc    = (const float*)d_in[0];
    }

    int prep_items = NB*QQ + NB*P;  // 34434
    prep_kernel<<<(prep_items + 255)/256, 256>>>(verts, pc);

    chamfer_kernel<<<CTAS_TOT, BLK>>>();

    finalize_kernel<<<1, 32>>>((float*)d_out);
}

// round 5
// speedup vs baseline: 2.0813x; 1.4277x over previous
#include <cuda_runtime.h>

#define NB 2
#define P  8192
#define HH 48
#define WW 48
#define RH 95
#define RW 95
#define QQ (RH*RW)          // 9025
#define TILE 2048           // SoA tile: 4 arrays x 2048 floats = 32KB
#define BLK 256
#define RPT 2               // a-points per thread (strided by BLK)
#define APC (BLK*RPT)       // 512 a-points per CTA

#define HALF_A ((QQ+1)/2)   // 4513 : split point of mesh b-cloud (dir A)
#define HALF_B (P/2)        // 4096 : split point of pc b-cloud (dir B)

#define XB_A (P/APC)                    // 16 x-blocks per batch, dir A
#define XB_B ((QQ + APC - 1)/APC)       // 18 x-blocks per batch, dir B
#define CTAS_A (2*NB*XB_A)              // 64  (S=2 splits)
#define CTAS_B (2*NB*XB_B)              // 72
#define CTAS_TOT (CTAS_A + CTAS_B)      // 136

#define NA_TOT (NB*P)       // 16384
#define NBQ_TOT (NB*QQ)     // 18050
#define FIN_ITEMS (NA_TOT + NBQ_TOT)    // 34434
#define FIN_BLKS ((FIN_ITEMS + 255)/256)  // 135

// scratch (allocation-free rule: __device__ globals)
__device__ float4 g_mesh[NBQ_TOT];
__device__ float4 g_pc[NA_TOT];
__device__ float  g_bestA[2][NA_TOT];   // per-split max_s for pc->mesh
__device__ float  g_bestB[2][NBQ_TOT];  // per-split max_s for mesh->pc
__device__ float  g_fpart[FIN_BLKS];

// ---------------------------------------------------------------------------
// f32x2 packed helpers
// ---------------------------------------------------------------------------
__device__ __forceinline__ unsigned long long fma2(unsigned long long a,
                                                   unsigned long long b,
                                                   unsigned long long c)
{
    unsigned long long d;
    asm("fma.rn.f32x2 %0, %1, %2, %3;" : "=l"(d) : "l"(a), "l"(b), "l"(c));
    return d;
}
__device__ __forceinline__ unsigned long long pack2(float x, float y)
{
    unsigned long long r;
    asm("mov.b64 %0, {%1,%2};" : "=l"(r) : "f"(x), "f"(y));
    return r;
}
__device__ __forceinline__ float2 u2f(unsigned long long v)
{
    float2 r;
    asm("mov.b64 {%0,%1}, %2;" : "=f"(r.x), "=f"(r.y) : "l"(v));
    return r;
}

// ---------------------------------------------------------------------------
// prep: refine mesh (midpoint bilinear, align_corners) + pack clouds as
// float4(x, y, z, 0.5*|v|^2)
// ---------------------------------------------------------------------------
__global__ void prep_kernel(const float* __restrict__ verts,
                            const float* __restrict__ pc)
{
    int idx = blockIdx.x * blockDim.x + threadIdx.x;
    if (idx < NBQ_TOT) {
        int n = idx / QQ;
        int r = idx % QQ;
        int i = r / RW, j = r % RW;
        int i0 = i >> 1, j0 = j >> 1;
        int oi = i & 1,  oj = j & 1;
        const float* base = verts + n * 3 * HH * WW;
        float vv[3];
        #pragma unroll
        for (int c = 0; c < 3; c++) {
            const float* pl = base + c * HH * WW;
            float v00 = pl[i0*WW + j0];
            float top = v00;
            if (oj) top = 0.5f * (v00 + pl[i0*WW + j0 + 1]);
            float val = top;
            if (oi) {
                float v10 = pl[(i0+1)*WW + j0];
                float bot = v10;
                if (oj) bot = 0.5f * (v10 + pl[(i0+1)*WW + j0 + 1]);
                val = 0.5f * (top + bot);
            }
            vv[c] = val;
        }
        g_mesh[idx] = make_float4(vv[0], vv[1], vv[2],
                                  0.5f*(vv[0]*vv[0] + vv[1]*vv[1] + vv[2]*vv[2]));
    } else {
        int idx2 = idx - NBQ_TOT;
        if (idx2 < NA_TOT) {
            const float* s = pc + (size_t)idx2 * 3;
            float x = s[0], y = s[1], z = s[2];
            g_pc[idx2] = make_float4(x, y, z, 0.5f*(x*x + y*y + z*z));
        }
    }
}

// ---------------------------------------------------------------------------
// One chamfer direction over one b-split.
//   s = a.b - 0.5|b|^2 ; best = max_b s  (min_d formed later in finalize)
// Thread tid owns a-points (a_off + tid) and (a_off + BLK + tid).
// Inner loop: SoA broadcast tile, f32x2 packed, 8 b-points per iteration.
// ---------------------------------------------------------------------------
__device__ __forceinline__ void chamfer_quad(
    unsigned long long ax0, unsigned long long ay0, unsigned long long az0,
    unsigned long long ax1, unsigned long long ay1, unsigned long long az1,
    const float* sbx, const float* sby, const float* sbz, const float* sbw,
    int t, float& m0a, float& m0b, float& m1a, float& m1b)
{
    ulonglong2 X = *(const ulonglong2*)(sbx + t);
    ulonglong2 Y = *(const ulonglong2*)(sby + t);
    ulonglong2 Z = *(const ulonglong2*)(sbz + t);
    ulonglong2 W = *(const ulonglong2*)(sbw + t);

    unsigned long long s;
    float2 f;
    s = fma2(az0, Z.x, W.x); s = fma2(ay0, Y.x, s); s = fma2(ax0, X.x, s);
    f = u2f(s); m0a = fmaxf(m0a, f.x); m0b = fmaxf(m0b, f.y);
    s = fma2(az0, Z.y, W.y); s = fma2(ay0, Y.y, s); s = fma2(ax0, X.y, s);
    f = u2f(s); m0a = fmaxf(m0a, f.x); m0b = fmaxf(m0b, f.y);
    s = fma2(az1, Z.x, W.x); s = fma2(ay1, Y.x, s); s = fma2(ax1, X.x, s);
    f = u2f(s); m1a = fmaxf(m1a, f.x); m1b = fmaxf(m1b, f.y);
    s = fma2(az1, Z.y, W.y); s = fma2(ay1, Y.y, s); s = fma2(ax1, X.y, s);
    f = u2f(s); m1a = fmaxf(m1a, f.x); m1b = fmaxf(m1b, f.y);
}

__device__ __forceinline__ void chamfer_dir(const float4* __restrict__ An,
                                            int nA, int a_off,
                                            const float4* __restrict__ Bn,
                                            int b_lo, int b_hi,
                                            float* __restrict__ best_out)
{
    __shared__ __align__(16) float sbx[TILE];
    __shared__ __align__(16) float sby[TILE];
    __shared__ __align__(16) float sbz[TILE];
    __shared__ __align__(16) float sbw[TILE];

    int tid = threadIdx.x;
    int i0 = a_off + tid;
    int i1 = a_off + BLK + tid;
    int j0 = i0 < nA ? i0 : nA - 1;
    int j1 = i1 < nA ? i1 : nA - 1;
    float4 a0 = An[j0];
    float4 a1 = An[j1];

    unsigned long long ax0 = pack2(a0.x, a0.x), ay0 = pack2(a0.y, a0.y), az0 = pack2(a0.z, a0.z);
    unsigned long long ax1 = pack2(a1.x, a1.x), ay1 = pack2(a1.y, a1.y), az1 = pack2(a1.z, a1.z);

    float m0a = -3.0e38f, m0b = -3.0e38f;
    float m1a = -3.0e38f, m1b = -3.0e38f;

    for (int q0 = b_lo; q0 < b_hi; q0 += TILE) {
        int cnt  = min(TILE, b_hi - q0);
        int cntp = (cnt + 7) & ~7;           // pad to multiple of 8
        __syncthreads();
        for (int t = tid; t < cntp; t += BLK) {
            if (t < cnt) {
                float4 b = Bn[q0 + t];
                sbx[t] = b.x; sby[t] = b.y; sbz[t] = b.z; sbw[t] = -b.w;
            } else {
                sbx[t] = 0.0f; sby[t] = 0.0f; sbz[t] = 0.0f; sbw[t] = -3.0e38f;
            }
        }
        __syncthreads();

        #pragma unroll 1
        for (int t = 0; t < cntp; t += 8) {
            chamfer_quad(ax0, ay0, az0, ax1, ay1, az1,
                         sbx, sby, sbz, sbw, t,     m0a, m0b, m1a, m1b);
            chamfer_quad(ax0, ay0, az0, ax1, ay1, az1,
                         sbx, sby, sbz, sbw, t + 4, m0a, m0b, m1a, m1b);
        }
    }

    if (i0 < nA) best_out[i0] = fmaxf(m0a, m0b);
    if (i1 < nA) best_out[i1] = fmaxf(m1a, m1b);
}

// ---------------------------------------------------------------------------
// Combined chamfer: both directions x batches x b-splits, one grid (136 CTAs)
// ---------------------------------------------------------------------------
__global__ void __launch_bounds__(BLK, 1) chamfer_kernel()
{
    int bid = blockIdx.x;
    if (bid < CTAS_A) {
        int s   = bid / (NB*XB_A);          // b-split 0/1
        int rem = bid % (NB*XB_A);
        int n   = rem / XB_A;
        int xb  = rem % XB_A;
        int b_lo = s ? HALF_A : 0;
        int b_hi = s ? QQ     : HALF_A;
        chamfer_dir(g_pc + n*P, P, xb*APC,
                    g_mesh + n*QQ, b_lo, b_hi,
                    &g_bestA[s][n*P]);
    } else {
        int b2  = bid - CTAS_A;
        int s   = b2 / (NB*XB_B);
        int rem = b2 % (NB*XB_B);
        int n   = rem / XB_B;
        int xb  = rem % XB_B;
        int b_lo = s ? HALF_B : 0;
        int b_hi = s ? P      : HALF_B;
        chamfer_dir(g_mesh + n*QQ, QQ, xb*APC,
                    g_pc + n*P, b_lo, b_hi,
                    &g_bestB[s][n*QQ]);
    }
}

// ---------------------------------------------------------------------------
// finalize stage 1: combine splits, form min_d, per-block partial sums
// ---------------------------------------------------------------------------
__global__ void finalize1_kernel()
{
    __shared__ float sh[8];
    int idx = blockIdx.x * 256 + threadIdx.x;
    float v = 0.0f;
    if (idx < NA_TOT) {
        float best = fmaxf(g_bestA[0][idx], g_bestA[1][idx]);
        v = 2.0f * (g_pc[idx].w - best) * (1.0f/NA_TOT);
    } else if (idx < FIN_ITEMS) {
        int k = idx - NA_TOT;
        float best = fmaxf(g_bestB[0][k], g_bestB[1][k]);
        v = 2.0f * (g_mesh[k].w - best) * (1.0f/NBQ_TOT);
    }
    #pragma unroll
    for (int o = 16; o > 0; o >>= 1) v += __shfl_down_sync(0xffffffffu, v, o);
    int lane = threadIdx.x & 31, wid = threadIdx.x >> 5;
    if (lane == 0) sh[wid] = v;
    __syncthreads();
    if (wid == 0) {
        v = (lane < 8) ? sh[lane] : 0.0f;
        #pragma unroll
        for (int o = 4; o > 0; o >>= 1) v += __shfl_down_sync(0xffffffffu, v, o);
        if (lane == 0) g_fpart[blockIdx.x] = v;
    }
}

// ---------------------------------------------------------------------------
// finalize stage 2: reduce the 135 partials
// ---------------------------------------------------------------------------
__global__ void finalize2_kernel(float* __restrict__ out)
{
    float v = 0.0f;
    int tid = threadIdx.x;
    for (int i = tid; i < FIN_BLKS; i += 32) v += g_fpart[i];
    #pragma unroll
    for (int o = 16; o > 0; o >>= 1) v += __shfl_down_sync(0xffffffffu, v, o);
    if (tid == 0) out[0] = v;
}

extern "C" void kernel_launch(void* const* d_in, const int* in_sizes, int n_in,
                              void* d_out, int out_size)
{
    // resolve inputs by size: vertices = 2*3*48*48 = 13824, pc = 2*8192*3 = 49152
    const float* verts = (const float*)d_in[0];
    const float* pc    = (const float*)d_in[1];
    if (n_in >= 2 && in_sizes[0] != NB*3*HH*WW) {
        verts = (const float*)d_in[1];
        pc    = (const float*)d_in[0];
    }

    int prep_items = NBQ_TOT + NA_TOT;  // 34434
    prep_kernel<<<(prep_items + 255)/256, 256>>>(verts, pc);

    chamfer_kernel<<<CTAS_TOT, BLK>>>();

    finalize1_kernel<<<FIN_BLKS, 256>>>();
    finalize2_kernel<<<1, 32>>>((float*)d_out);
}

// round 6
// speedup vs baseline: 2.4774x; 1.1903x over previous
#include <cuda_runtime.h>

#define NB 2
#define P  8192
#define HH 48
#define WW 48
#define RH 95
#define RW 95
#define QQ (RH*RW)          // 9025
#define TILE 2048           // SoA tile: 4 arrays x 2048 floats = 32KB
#define BLK 512
#define RPT 2               // a-points per thread (strided by BLK)
#define APC (BLK*RPT)       // 1024 a-points per CTA
#define NSPLIT 4            // b-cloud splits

#define XB_A (P/APC)                    // 8 x-blocks per batch, dir A
#define XB_B ((QQ + APC - 1)/APC)       // 9 x-blocks per batch, dir B
#define CTAS_A (NSPLIT*NB*XB_A)         // 64
#define CTAS_B (NSPLIT*NB*XB_B)         // 72
#define CTAS_TOT (CTAS_A + CTAS_B)      // 136

#define NA_TOT (NB*P)       // 16384
#define NBQ_TOT (NB*QQ)     // 18050
#define FIN_ITEMS (NA_TOT + NBQ_TOT)    // 34434
#define FIN_BLK 1024
#define FIN_BLKS ((FIN_ITEMS + FIN_BLK - 1)/FIN_BLK)  // 34

// scratch (allocation-free rule: __device__ globals)
__device__ float4 g_mesh[NBQ_TOT];
__device__ float4 g_pc[NA_TOT];
__device__ float  g_bestA[NSPLIT][NA_TOT];   // per-split max_s for pc->mesh
__device__ float  g_bestB[NSPLIT][NBQ_TOT];  // per-split max_s for mesh->pc
__device__ float  g_fpart[FIN_BLKS];
__device__ int    g_done;                    // reset by prep each replay

// ---------------------------------------------------------------------------
// f32x2 packed helpers
// ---------------------------------------------------------------------------
__device__ __forceinline__ unsigned long long fma2(unsigned long long a,
                                                   unsigned long long b,
                                                   unsigned long long c)
{
    unsigned long long d;
    asm("fma.rn.f32x2 %0, %1, %2, %3;" : "=l"(d) : "l"(a), "l"(b), "l"(c));
    return d;
}
__device__ __forceinline__ unsigned long long pack2(float x, float y)
{
    unsigned long long r;
    asm("mov.b64 %0, {%1,%2};" : "=l"(r) : "f"(x), "f"(y));
    return r;
}
__device__ __forceinline__ float2 u2f(unsigned long long v)
{
    float2 r;
    asm("mov.b64 {%0,%1}, %2;" : "=f"(r.x), "=f"(r.y) : "l"(v));
    return r;
}

// ---------------------------------------------------------------------------
// prep: refine mesh (midpoint bilinear, align_corners) + pack clouds as
// float4(x, y, z, 0.5*|v|^2). Also resets the finalize completion counter.
// ---------------------------------------------------------------------------
__global__ void prep_kernel(const float* __restrict__ verts,
                            const float* __restrict__ pc)
{
    int idx = blockIdx.x * blockDim.x + threadIdx.x;
    if (idx == 0) g_done = 0;
    if (idx < NBQ_TOT) {
        int n = idx / QQ;
        int r = idx % QQ;
        int i = r / RW, j = r % RW;
        int i0 = i >> 1, j0 = j >> 1;
        int oi = i & 1,  oj = j & 1;
        const float* base = verts + n * 3 * HH * WW;
        float vv[3];
        #pragma unroll
        for (int c = 0; c < 3; c++) {
            const float* pl = base + c * HH * WW;
            float v00 = pl[i0*WW + j0];
            float top = v00;
            if (oj) top = 0.5f * (v00 + pl[i0*WW + j0 + 1]);
            float val = top;
            if (oi) {
                float v10 = pl[(i0+1)*WW + j0];
                float bot = v10;
                if (oj) bot = 0.5f * (v10 + pl[(i0+1)*WW + j0 + 1]);
                val = 0.5f * (top + bot);
            }
            vv[c] = val;
        }
        g_mesh[idx] = make_float4(vv[0], vv[1], vv[2],
                                  0.5f*(vv[0]*vv[0] + vv[1]*vv[1] + vv[2]*vv[2]));
    } else {
        int idx2 = idx - NBQ_TOT;
        if (idx2 < NA_TOT) {
            const float* s = pc + (size_t)idx2 * 3;
            float x = s[0], y = s[1], z = s[2];
            g_pc[idx2] = make_float4(x, y, z, 0.5f*(x*x + y*y + z*z));
        }
    }
}

// ---------------------------------------------------------------------------
// One chamfer direction over one b-split.
//   s = a.b - 0.5|b|^2 ; best = max_b s  (min_d formed later in finalize)
// Thread tid owns a-points (a_off + tid) and (a_off + BLK + tid).
// Inner loop: SoA broadcast tile, f32x2 packed, 8 b-points per iteration.
// ---------------------------------------------------------------------------
__device__ __forceinline__ void chamfer_quad(
    unsigned long long ax0, unsigned long long ay0, unsigned long long az0,
    unsigned long long ax1, unsigned long long ay1, unsigned long long az1,
    const float* sbx, const float* sby, const float* sbz, const float* sbw,
    int t, float& m0a, float& m0b, float& m1a, float& m1b)
{
    ulonglong2 X = *(const ulonglong2*)(sbx + t);
    ulonglong2 Y = *(const ulonglong2*)(sby + t);
    ulonglong2 Z = *(const ulonglong2*)(sbz + t);
    ulonglong2 W = *(const ulonglong2*)(sbw + t);

    unsigned long long s;
    float2 f;
    s = fma2(az0, Z.x, W.x); s = fma2(ay0, Y.x, s); s = fma2(ax0, X.x, s);
    f = u2f(s); m0a = fmaxf(m0a, f.x); m0b = fmaxf(m0b, f.y);
    s = fma2(az0, Z.y, W.y); s = fma2(ay0, Y.y, s); s = fma2(ax0, X.y, s);
    f = u2f(s); m0a = fmaxf(m0a, f.x); m0b = fmaxf(m0b, f.y);
    s = fma2(az1, Z.x, W.x); s = fma2(ay1, Y.x, s); s = fma2(ax1, X.x, s);
    f = u2f(s); m1a = fmaxf(m1a, f.x); m1b = fmaxf(m1b, f.y);
    s = fma2(az1, Z.y, W.y); s = fma2(ay1, Y.y, s); s = fma2(ax1, X.y, s);
    f = u2f(s); m1a = fmaxf(m1a, f.x); m1b = fmaxf(m1b, f.y);
}

__device__ __forceinline__ void chamfer_dir(const float4* __restrict__ An,
                                            int nA, int a_off,
                                            const float4* __restrict__ Bn,
                                            int b_lo, int b_hi,
                                            float* __restrict__ best_out)
{
    __shared__ __align__(16) float sbx[TILE];
    __shared__ __align__(16) float sby[TILE];
    __shared__ __align__(16) float sbz[TILE];
    __shared__ __align__(16) float sbw[TILE];

    int tid = threadIdx.x;
    int i0 = a_off + tid;
    int i1 = a_off + BLK + tid;
    int j0 = i0 < nA ? i0 : nA - 1;
    int j1 = i1 < nA ? i1 : nA - 1;
    float4 a0 = An[j0];
    float4 a1 = An[j1];

    unsigned long long ax0 = pack2(a0.x, a0.x), ay0 = pack2(a0.y, a0.y), az0 = pack2(a0.z, a0.z);
    unsigned long long ax1 = pack2(a1.x, a1.x), ay1 = pack2(a1.y, a1.y), az1 = pack2(a1.z, a1.z);

    float m0a = -3.0e38f, m0b = -3.0e38f;
    float m1a = -3.0e38f, m1b = -3.0e38f;

    for (int q0 = b_lo; q0 < b_hi; q0 += TILE) {
        int cnt  = min(TILE, b_hi - q0);
        int cntp = (cnt + 7) & ~7;           // pad to multiple of 8
        __syncthreads();
        for (int t = tid; t < cntp; t += BLK) {
            if (t < cnt) {
                float4 b = Bn[q0 + t];
                sbx[t] = b.x; sby[t] = b.y; sbz[t] = b.z; sbw[t] = -b.w;
            } else {
                sbx[t] = 0.0f; sby[t] = 0.0f; sbz[t] = 0.0f; sbw[t] = -3.0e38f;
            }
        }
        __syncthreads();

        #pragma unroll 1
        for (int t = 0; t < cntp; t += 8) {
            chamfer_quad(ax0, ay0, az0, ax1, ay1, az1,
                         sbx, sby, sbz, sbw, t,     m0a, m0b, m1a, m1b);
            chamfer_quad(ax0, ay0, az0, ax1, ay1, az1,
                         sbx, sby, sbz, sbw, t + 4, m0a, m0b, m1a, m1b);
        }
    }

    if (i0 < nA) best_out[i0] = fmaxf(m0a, m0b);
    if (i1 < nA) best_out[i1] = fmaxf(m1a, m1b);
}

// ---------------------------------------------------------------------------
// Combined chamfer: directions x batches x b-splits, one grid (136 CTAs)
// ---------------------------------------------------------------------------
__global__ void __launch_bounds__(BLK, 1) chamfer_kernel()
{
    int bid = blockIdx.x;
    if (bid < CTAS_A) {
        int s   = bid / (NB*XB_A);          // b-split 0..3
        int rem = bid % (NB*XB_A);
        int n   = rem / XB_A;
        int xb  = rem % XB_A;
        int b_lo = ( s      * QQ) / NSPLIT;
        int b_hi = ((s + 1) * QQ) / NSPLIT;
        chamfer_dir(g_pc + n*P, P, xb*APC,
                    g_mesh + n*QQ, b_lo, b_hi,
                    &g_bestA[s][n*P]);
    } else {
        int b2  = bid - CTAS_A;
        int s   = b2 / (NB*XB_B);
        int rem = b2 % (NB*XB_B);
        int n   = rem / XB_B;
        int xb  = rem % XB_B;
        int b_lo = ( s      * P) / NSPLIT;
        int b_hi = ((s + 1) * P) / NSPLIT;
        chamfer_dir(g_mesh + n*QQ, QQ, xb*APC,
                    g_pc + n*P, b_lo, b_hi,
                    &g_bestB[s][n*QQ]);
    }
}

// ---------------------------------------------------------------------------
// finalize: combine splits, form min_d, reduce. Single kernel via
// last-block-done (deterministic: fixed-order final sum by one block).
// ---------------------------------------------------------------------------
__global__ void finalize_kernel(float* __restrict__ out)
{
    __shared__ float sh[32];
    __shared__ int   s_last;
    int idx = blockIdx.x * FIN_BLK + threadIdx.x;
    float v = 0.0f;
    if (idx < NA_TOT) {
        float best = fmaxf(fmaxf(g_bestA[0][idx], g_bestA[1][idx]),
                           fmaxf(g_bestA[2][idx], g_bestA[3][idx]));
        v = 2.0f * (g_pc[idx].w - best) * (1.0f/NA_TOT);
    } else if (idx < FIN_ITEMS) {
        int k = idx - NA_TOT;
        float best = fmaxf(fmaxf(g_bestB[0][k], g_bestB[1][k]),
                           fmaxf(g_bestB[2][k], g_bestB[3][k]));
        v = 2.0f * (g_mesh[k].w - best) * (1.0f/NBQ_TOT);
    }
    #pragma unroll
    for (int o = 16; o > 0; o >>= 1) v += __shfl_down_sync(0xffffffffu, v, o);
    int lane = threadIdx.x & 31, wid = threadIdx.x >> 5;
    if (lane == 0) sh[wid] = v;
    __syncthreads();
    if (wid == 0) {
        v = sh[lane];   // FIN_BLK/32 = 32 warps exactly
        #pragma unroll
        for (int o = 16; o > 0; o >>= 1) v += __shfl_down_sync(0xffffffffu, v, o);
        if (lane == 0) {
            g_fpart[blockIdx.x] = v;
            __threadfence();
            int t = atomicAdd(&g_done, 1);
            s_last = (t == FIN_BLKS - 1);
        }
    }
    __syncthreads();
    if (s_last && wid == 0) {
        float r = 0.0f;
        if (lane == 0) {
            #pragma unroll
            for (int i = 0; i < FIN_BLKS; i++) r += g_fpart[i];
            out[0] = r;
        }
    }
}

extern "C" void kernel_launch(void* const* d_in, const int* in_sizes, int n_in,
                              void* d_out, int out_size)
{
    // resolve inputs by size: vertices = 2*3*48*48 = 13824, pc = 2*8192*3 = 49152
    const float* verts = (const float*)d_in[0];
    const float* pc    = (const float*)d_in[1];
    if (n_in >= 2 && in_sizes[0] != NB*3*HH*WW) {
        verts = (const float*)d_in[1];
        pc    = (const float*)d_in[0];
    }

    int prep_items = NBQ_TOT + NA_TOT;  // 34434
    prep_kernel<<<(prep_items + 255)/256, 256>>>(verts, pc);

    chamfer_kernel<<<CTAS_TOT, BLK>>>();

    finalize_kernel<<<FIN_BLKS, FIN_BLK>>>((float*)d_out);
}